// round 7
// baseline (speedup 1.0000x reference)
#include <cuda_runtime.h>
#include <cuda_fp16.h>
#include <cstdint>

// ============================================================================
// CirculantLinear via length-4 real DFT diagonalization (sm_103-safe ISA only:
// cp.async + ldmatrix + mma.sync.m16n8k16.f16 — NO tcgen05/TMA, the harness
// builds through virtual arch compute_103 which rejects all "a" features).
//
//   x (4096x4096 f32), eigens (1024x1024x4 f32) -> out (4096x4096 f32)
//   prep_x : x -> Xt = [X0|X2|Xr|Xi]  (half)
//   prep_w : eigens -> W0, W2 (1024x1024), W1 (2048x2048 = [[Er,-Ei],[Ei,Er]])
//   3x f16 GEMM (f32 accum):  Yt[:,0:1024]   = Xt0 * W0^T
//                             Yt[:,1024:2048]= Xt2 * W2^T
//                             Yt[:,2048:4096]= [Xr|Xi] * W1^T
//   post   : inverse length-4 rDFT -> out
// ============================================================================

// ------------------------- device scratch (static) --------------------------
__device__ __half g_Xt[(size_t)4096 * 4096];   // 32 MB
__device__ __half g_W0[1024 * 1024];           // 2 MB
__device__ __half g_W2[1024 * 1024];           // 2 MB
__device__ __half g_W1[(size_t)2048 * 2048];   // 8 MB
__device__ float  g_Yt[(size_t)4096 * 4096];   // 64 MB

// ------------------------- PTX helpers --------------------------------------
__device__ __forceinline__ uint32_t smem_u32(const void* p) {
    uint32_t a;
    asm("{ .reg .u64 t; cvta.to.shared.u64 t, %1; cvt.u32.u64 %0, t; }"
        : "=r"(a) : "l"(p));
    return a;
}

__device__ __forceinline__ void cp_async16(uint32_t dst, const void* src) {
    asm volatile("cp.async.cg.shared.global [%0], [%1], 16;"
                 :: "r"(dst), "l"(src) : "memory");
}
#define CP_COMMIT() asm volatile("cp.async.commit_group;" ::: "memory")
#define CP_WAIT(N)  asm volatile("cp.async.wait_group %0;" :: "n"(N) : "memory")

__device__ __forceinline__ void ldsm_x4(uint32_t r[4], uint32_t addr) {
    asm volatile("ldmatrix.sync.aligned.m8n8.x4.shared.b16 {%0,%1,%2,%3}, [%4];"
                 : "=r"(r[0]), "=r"(r[1]), "=r"(r[2]), "=r"(r[3]) : "r"(addr));
}

__device__ __forceinline__ void mma16816(float c[4], const uint32_t a[4],
                                         const uint32_t b[2]) {
    asm volatile(
        "mma.sync.aligned.m16n8k16.row.col.f32.f16.f16.f32 "
        "{%0,%1,%2,%3}, {%4,%5,%6,%7}, {%8,%9}, {%0,%1,%2,%3};"
        : "+f"(c[0]), "+f"(c[1]), "+f"(c[2]), "+f"(c[3])
        : "r"(a[0]), "r"(a[1]), "r"(a[2]), "r"(a[3]), "r"(b[0]), "r"(b[1]));
}

// ------------------------- GEMM kernel --------------------------------------
// CTA tile 128x128, BK=32 halfs, 4-stage cp.async pipeline.
// 8 warps as 4(M) x 2(N): warp tile 32x64 -> 2 mtiles x 8 ntiles of m16n8k16.
// smem rows padded to 40 halfs (80 B) => conflict-free ldmatrix.
static constexpr int BM = 128, BN = 128, BK = 32, STAGES = 4;
static constexpr int LDS_ROW   = 40;                    // halfs (80 B)
static constexpr int AB_BYTES  = 128 * LDS_ROW * 2;     // 10240 per operand
static constexpr int STG_BYTES = 2 * AB_BYTES;          // 20480 per stage
static constexpr int SMEM_GEMM = STAGES * STG_BYTES;    // 81920

__global__ void __launch_bounds__(256, 1) gemm_f16(
    const __half* __restrict__ A, int lda,    // [M, K] row-major (k contig)
    const __half* __restrict__ B, int ldb,    // [N, K] row-major (k contig)
    float* __restrict__ C, int ldc, int nk)   // C: [M, ldc], nk = K/32
{
    extern __shared__ __align__(128) char smem[];
    const uint32_t sb = smem_u32(smem);
    const int tid  = threadIdx.x;
    const int wid  = tid >> 5;
    const int lane = tid & 31;
    const int m0 = blockIdx.x * BM;
    const int n0 = blockIdx.y * BN;
    const int wm = wid & 3;          // 0..3 -> M offset wm*32
    const int wn = wid >> 2;         // 0..1 -> N offset wn*64

    const __half* Abase = A + (size_t)m0 * lda;
    const __half* Bbase = B + (size_t)n0 * ldb;

    // --- stage loader: 512 x 16B segs each for A and B, 2 per thread ---
    auto load_stage = [&](int s, int kt) {
        const uint32_t st = sb + s * STG_BYTES;
        const __half* Ag = Abase + kt * BK;
        const __half* Bg = Bbase + kt * BK;
        #pragma unroll
        for (int i = 0; i < 2; i++) {
            int seg = i * 256 + tid;          // 0..511
            int row = seg >> 2, c = seg & 3;  // row 0..127, 16B chunk 0..3
            uint32_t so = row * 80 + c * 16;
            cp_async16(st + so,            Ag + (size_t)row * lda + c * 8);
            cp_async16(st + AB_BYTES + so, Bg + (size_t)row * ldb + c * 8);
        }
    };

    float acc[2][8][4];
    #pragma unroll
    for (int mt = 0; mt < 2; mt++)
        #pragma unroll
        for (int nt = 0; nt < 8; nt++)
            #pragma unroll
            for (int i = 0; i < 4; i++) acc[mt][nt][i] = 0.0f;

    // precomputed ldmatrix lane address offsets (halfs)
    const int a_row = wm * 32 + (lane & 15);          // + mt*16
    const int a_kh  = (lane >> 4) << 3;               // + ks*16
    const int b_row = wn * 64 + (lane & 7) + ((lane >> 1) & 8);   // + np*16
    const int b_kh  = lane & 8;                       // + ks*16

    // --- prologue ---
    #pragma unroll
    for (int s = 0; s < STAGES - 1; s++) {
        load_stage(s, s);
        CP_COMMIT();
    }

    // --- mainloop ---
    for (int kt = 0; kt < nk; kt++) {
        CP_WAIT(STAGES - 2);
        __syncthreads();

        const uint32_t As = sb + (kt & (STAGES - 1)) * STG_BYTES;
        const uint32_t Bs = As + AB_BYTES;

        #pragma unroll
        for (int ks = 0; ks < 2; ks++) {
            uint32_t afr[2][4];
            #pragma unroll
            for (int mt = 0; mt < 2; mt++)
                ldsm_x4(afr[mt],
                        As + ((a_row + mt * 16) * 80 + (a_kh + ks * 16) * 2));
            uint32_t bfr[8][2];
            #pragma unroll
            for (int np = 0; np < 4; np++) {
                uint32_t r[4];
                ldsm_x4(r, Bs + ((b_row + np * 16) * 80 + (b_kh + ks * 16) * 2));
                bfr[np * 2 + 0][0] = r[0]; bfr[np * 2 + 0][1] = r[1];
                bfr[np * 2 + 1][0] = r[2]; bfr[np * 2 + 1][1] = r[3];
            }
            #pragma unroll
            for (int mt = 0; mt < 2; mt++)
                #pragma unroll
                for (int nt = 0; nt < 8; nt++)
                    mma16816(acc[mt][nt], afr[mt], bfr[nt]);
        }
        __syncthreads();

        int kn = kt + STAGES - 1;
        if (kn < nk) load_stage(kn & (STAGES - 1), kn);
        CP_COMMIT();
    }

    // --- epilogue: direct f32 stores ---
    const int g = lane >> 2, t = lane & 3;
    #pragma unroll
    for (int mt = 0; mt < 2; mt++) {
        int row = m0 + wm * 32 + mt * 16 + g;
        #pragma unroll
        for (int nt = 0; nt < 8; nt++) {
            int col = n0 + wn * 64 + nt * 8 + 2 * t;
            float2 v0 = make_float2(acc[mt][nt][0], acc[mt][nt][1]);
            float2 v1 = make_float2(acc[mt][nt][2], acc[mt][nt][3]);
            *reinterpret_cast<float2*>(C + (size_t)row * ldc + col)       = v0;
            *reinterpret_cast<float2*>(C + (size_t)(row + 8) * ldc + col) = v1;
        }
    }
}

// ------------------------- transform kernels --------------------------------
// Forward rDFT-4: X0=x0+x1+x2+x3, X2=x0-x1+x2-x3, Xr=x0-x2, Xi=x3-x1
__global__ void prep_x_kernel(const float* __restrict__ x) {
    int t = blockIdx.x * blockDim.x + threadIdx.x;
    if (t >= 4096 * 1024) return;
    int b = t >> 10, g = t & 1023;
    float4 v = *reinterpret_cast<const float4*>(x + ((size_t)b << 12) + (g << 2));
    float e = v.x + v.z, o = v.y + v.w;
    __half* r = g_Xt + ((size_t)b << 12);
    r[g]        = __float2half_rn(e + o);
    r[1024 + g] = __float2half_rn(e - o);
    r[2048 + g] = __float2half_rn(v.x - v.z);
    r[3072 + g] = __float2half_rn(v.w - v.y);
}

// Eigens -> W0, W2, W1 (complex bin packed as [[Er,-Ei],[Ei,Er]])
__global__ void prep_w_kernel(const float* __restrict__ eg) {
    int t = blockIdx.x * blockDim.x + threadIdx.x;
    if (t >= 1024 * 1024) return;
    int y = t >> 10, xg = t & 1023;
    float4 v = *reinterpret_cast<const float4*>(eg + ((size_t)t << 2));
    float e = v.x + v.z, o = v.y + v.w;
    __half Er  = __float2half_rn(v.x - v.z);
    __half Ei  = __float2half_rn(v.w - v.y);
    __half nEi = __float2half_rn(v.y - v.w);
    g_W0[t] = __float2half_rn(e + o);
    g_W2[t] = __float2half_rn(e - o);
    size_t r1 = (size_t)y * 2048;
    size_t r2 = (size_t)(1024 + y) * 2048;
    g_W1[r1 + xg]        = Er;
    g_W1[r1 + 1024 + xg] = nEi;
    g_W1[r2 + xg]        = Ei;
    g_W1[r2 + 1024 + xg] = Er;
}

// Inverse rDFT-4: out_j = (Y0 + (-1)^j Y2 + 2 Re(Y1 i^j)) / 4
__global__ void post_kernel(float* __restrict__ out) {
    int t = blockIdx.x * blockDim.x + threadIdx.x;
    if (t >= 4096 * 1024) return;
    int b = t >> 10, y = t & 1023;
    const float* r = g_Yt + ((size_t)b << 12);
    float Y0 = r[y], Y2 = r[1024 + y], Yr = r[2048 + y], Yi = r[3072 + y];
    float4 o;
    o.x = 0.25f * (Y0 + Y2 + 2.0f * Yr);
    o.y = 0.25f * (Y0 - Y2 - 2.0f * Yi);
    o.z = 0.25f * (Y0 + Y2 - 2.0f * Yr);
    o.w = 0.25f * (Y0 - Y2 + 2.0f * Yi);
    *reinterpret_cast<float4*>(out + ((size_t)b << 12) + (y << 2)) = o;
}

// ------------------------- host side ----------------------------------------
extern "C" void kernel_launch(void* const* d_in, const int* in_sizes, int n_in,
                              void* d_out, int out_size)
{
    const float* x  = (const float*)d_in[0];
    const float* eg = (const float*)d_in[1];
    if (n_in >= 2 && in_sizes[0] < in_sizes[1]) {   // x: 16.8M elems, eigens: 4.2M
        const float* t = x; x = eg; eg = t;
    }

    void *pXt, *pW0, *pW2, *pW1, *pYt;
    cudaGetSymbolAddress(&pXt, g_Xt);
    cudaGetSymbolAddress(&pW0, g_W0);
    cudaGetSymbolAddress(&pW2, g_W2);
    cudaGetSymbolAddress(&pW1, g_W1);
    cudaGetSymbolAddress(&pYt, g_Yt);
    const __half* Xt = (const __half*)pXt;
    float* Yt = (float*)pYt;

    cudaFuncSetAttribute(gemm_f16, cudaFuncAttributeMaxDynamicSharedMemorySize,
                         SMEM_GEMM);

    prep_x_kernel<<<(4096 * 1024) / 256, 256>>>(x);
    prep_w_kernel<<<(1024 * 1024) / 256, 256>>>(eg);

    // Yt[:, 0:1024] = X0 * W0^T
    gemm_f16<<<dim3(32, 8), 256, SMEM_GEMM>>>(
        Xt + 0, 4096, (const __half*)pW0, 1024, Yt + 0, 4096, 1024 / BK);
    // Yt[:, 1024:2048] = X2 * W2^T
    gemm_f16<<<dim3(32, 8), 256, SMEM_GEMM>>>(
        Xt + 1024, 4096, (const __half*)pW2, 1024, Yt + 1024, 4096, 1024 / BK);
    // Yt[:, 2048:4096] = [Xr|Xi] * W1^T
    gemm_f16<<<dim3(32, 16), 256, SMEM_GEMM>>>(
        Xt + 2048, 4096, (const __half*)pW1, 2048, Yt + 2048, 4096, 2048 / BK);

    post_kernel<<<(4096 * 1024) / 256, 256>>>((float*)d_out);
}

// round 8
// speedup vs baseline: 1.5274x; 1.5274x over previous
#include <cuda_runtime.h>
#include <cuda_fp16.h>
#include <cstdint>

// ============================================================================
// CirculantLinear via length-4 real DFT diagonalization (sm_103-safe ISA:
// cp.async + ldmatrix + mma.sync.m16n8k16.f16; no tcgen05/TMA — harness
// compiles via compute_103 which rejects all "a"-suffix features).
//
//   x (4096x4096 f32), eigens (1024x1024x4 f32) -> out (4096x4096 f32)
//   prep_x : x -> Xt = [X0|X2|Xr|Xi]  (half)
//   prep_w : eigens -> W0, W2 (1024x1024), W1 (2048x2048 = [[Er,-Ei],[Ei,Er]])
//   ONE merged GEMM launch (1024 tiles, 3 logical GEMMs, f32 accum):
//       Yt[:,0:1024]   = X0 * W0^T
//       Yt[:,1024:2048]= X2 * W2^T
//       Yt[:,2048:4096]= [Xr|Xi] * W1^T
//   post   : inverse length-4 rDFT -> out
//
// R8: 3-stage pipeline + __launch_bounds__(256,2) => 2 CTA/SM (4 warps/SMSP),
//     single __syncthreads per mainloop iter, merged tile-table launch with
//     long-K tiles scheduled first.
// ============================================================================

// ------------------------- device scratch (static) --------------------------
__device__ __half g_Xt[(size_t)4096 * 4096];   // 32 MB
__device__ __half g_W0[1024 * 1024];           // 2 MB
__device__ __half g_W2[1024 * 1024];           // 2 MB
__device__ __half g_W1[(size_t)2048 * 2048];   // 8 MB
__device__ float  g_Yt[(size_t)4096 * 4096];   // 64 MB

// ------------------------- PTX helpers --------------------------------------
__device__ __forceinline__ uint32_t smem_u32(const void* p) {
    uint32_t a;
    asm("{ .reg .u64 t; cvta.to.shared.u64 t, %1; cvt.u32.u64 %0, t; }"
        : "=r"(a) : "l"(p));
    return a;
}

__device__ __forceinline__ void cp_async16(uint32_t dst, const void* src) {
    asm volatile("cp.async.cg.shared.global [%0], [%1], 16;"
                 :: "r"(dst), "l"(src) : "memory");
}
#define CP_COMMIT() asm volatile("cp.async.commit_group;" ::: "memory")
#define CP_WAIT(N)  asm volatile("cp.async.wait_group %0;" :: "n"(N) : "memory")

__device__ __forceinline__ void ldsm_x4(uint32_t r[4], uint32_t addr) {
    asm volatile("ldmatrix.sync.aligned.m8n8.x4.shared.b16 {%0,%1,%2,%3}, [%4];"
                 : "=r"(r[0]), "=r"(r[1]), "=r"(r[2]), "=r"(r[3]) : "r"(addr));
}

__device__ __forceinline__ void mma16816(float c[4], const uint32_t a[4],
                                         const uint32_t b[2]) {
    asm volatile(
        "mma.sync.aligned.m16n8k16.row.col.f32.f16.f16.f32 "
        "{%0,%1,%2,%3}, {%4,%5,%6,%7}, {%8,%9}, {%0,%1,%2,%3};"
        : "+f"(c[0]), "+f"(c[1]), "+f"(c[2]), "+f"(c[3])
        : "r"(a[0]), "r"(a[1]), "r"(a[2]), "r"(a[3]), "r"(b[0]), "r"(b[1]));
}

// ------------------------- merged GEMM kernel --------------------------------
// CTA tile 128x128, BK=32 halfs, 3-stage cp.async pipeline, 2 CTAs/SM.
// 8 warps as 4(M) x 2(N): warp tile 32x64 -> 2 mtiles x 8 ntiles of m16n8k16.
// smem rows padded to 40 halfs (80 B) => conflict-free ldmatrix.
static constexpr int BK = 32, STAGES = 3;
static constexpr int AB_BYTES  = 128 * 80;              // 10240 per operand
static constexpr int STG_BYTES = 2 * AB_BYTES;          // 20480 per stage
static constexpr int SMEM_GEMM = STAGES * STG_BYTES;    // 61440

// Tile table (1024 tiles):
//   t in [0,512):    W1 segment (nk=64) — scheduled FIRST (long tiles)
//   t in [512,768):  W0 segment (nk=32)
//   t in [768,1024): W2 segment (nk=32)
__global__ void __launch_bounds__(256, 2) gemm_f16_merged()
{
    extern __shared__ __align__(128) char smem[];
    const uint32_t sb = smem_u32(smem);
    const int tid  = threadIdx.x;
    const int wid  = tid >> 5;
    const int lane = tid & 31;

    // ---- tile decode ----
    const __half* A;           // [4096, 4096] row-major, column window per seg
    const __half* B;           // [N, K] row-major (k contiguous)
    float*        C;           // Yt column window
    int ldb, nk, m0, n0;
    {
        int t = blockIdx.x;
        if (t < 512) {                       // bin1: [Xr|Xi] * W1^T
            m0 = (t >> 4) * 128; n0 = (t & 15) * 128;
            A = g_Xt + 2048; B = g_W1; C = g_Yt + 2048; ldb = 2048; nk = 64;
        } else if (t < 768) {                // bin0: X0 * W0^T
            int u = t - 512;
            m0 = (u >> 3) * 128; n0 = (u & 7) * 128;
            A = g_Xt; B = g_W0; C = g_Yt; ldb = 1024; nk = 32;
        } else {                             // bin2: X2 * W2^T
            int u = t - 768;
            m0 = (u >> 3) * 128; n0 = (u & 7) * 128;
            A = g_Xt + 1024; B = g_W2; C = g_Yt + 1024; ldb = 1024; nk = 32;
        }
    }
    const int wm = wid & 3;          // M offset wm*32
    const int wn = wid >> 2;         // N offset wn*64

    const __half* Abase = A + (size_t)m0 * 4096;
    const __half* Bbase = B + (size_t)n0 * ldb;

    // --- stage loader: 512 x 16B segs each for A and B, 2 per thread ---
    auto load_stage = [&](int s, int kt) {
        const uint32_t st = sb + s * STG_BYTES;
        const __half* Ag = Abase + kt * BK;
        const __half* Bg = Bbase + kt * BK;
        #pragma unroll
        for (int i = 0; i < 2; i++) {
            int seg = i * 256 + tid;          // 0..511
            int row = seg >> 2, c = seg & 3;  // row 0..127, 16B chunk 0..3
            uint32_t so = row * 80 + c * 16;
            cp_async16(st + so,            Ag + (size_t)row * 4096 + c * 8);
            cp_async16(st + AB_BYTES + so, Bg + (size_t)row * ldb  + c * 8);
        }
    };

    float acc[2][8][4];
    #pragma unroll
    for (int mt = 0; mt < 2; mt++)
        #pragma unroll
        for (int nt = 0; nt < 8; nt++)
            #pragma unroll
            for (int i = 0; i < 4; i++) acc[mt][nt][i] = 0.0f;

    // precomputed ldmatrix lane address offsets (halfs)
    const int a_row = wm * 32 + (lane & 15);                      // + mt*16
    const int a_kh  = (lane >> 4) << 3;                           // + ks*16
    const int b_row = wn * 64 + (lane & 7) + ((lane >> 1) & 8);   // + np*16
    const int b_kh  = lane & 8;                                   // + ks*16

    // --- prologue: stages 0,1 ---
    load_stage(0, 0); CP_COMMIT();
    load_stage(1, 1); CP_COMMIT();

    // --- mainloop: ONE barrier per iteration ---
    // Slot math: compute reads slot kt%3; the load issued at iter kt targets
    // slot (kt+2)%3 == (kt-1)%3, whose readers (iter kt-1 compute) all
    // finished before this iter's __syncthreads. Race-free with one barrier.
    int slot = 0;
    for (int kt = 0; kt < nk; kt++) {
        CP_WAIT(1);
        __syncthreads();

        int kn = kt + 2;
        if (kn < nk) {
            int ls = slot + 2; if (ls >= 3) ls -= 3;
            load_stage(ls, kn);
        }
        CP_COMMIT();   // commit (possibly empty) keeps group accounting fixed

        const uint32_t As = sb + slot * STG_BYTES;
        const uint32_t Bs = As + AB_BYTES;

        #pragma unroll
        for (int ks = 0; ks < 2; ks++) {
            uint32_t afr[2][4];
            #pragma unroll
            for (int mt = 0; mt < 2; mt++)
                ldsm_x4(afr[mt],
                        As + ((a_row + mt * 16) * 80 + (a_kh + ks * 16) * 2));
            uint32_t bfr[8][2];
            #pragma unroll
            for (int np = 0; np < 4; np++) {
                uint32_t r[4];
                ldsm_x4(r, Bs + ((b_row + np * 16) * 80 + (b_kh + ks * 16) * 2));
                bfr[np * 2 + 0][0] = r[0]; bfr[np * 2 + 0][1] = r[1];
                bfr[np * 2 + 1][0] = r[2]; bfr[np * 2 + 1][1] = r[3];
            }
            #pragma unroll
            for (int mt = 0; mt < 2; mt++)
                #pragma unroll
                for (int nt = 0; nt < 8; nt++)
                    mma16816(acc[mt][nt], afr[mt], bfr[nt]);
        }

        if (++slot == 3) slot = 0;
    }

    // --- epilogue: direct f32 stores to Yt ---
    const int g = lane >> 2, t4 = lane & 3;
    #pragma unroll
    for (int mt = 0; mt < 2; mt++) {
        int row = m0 + wm * 32 + mt * 16 + g;
        #pragma unroll
        for (int nt = 0; nt < 8; nt++) {
            int col = n0 + wn * 64 + nt * 8 + 2 * t4;
            float2 v0 = make_float2(acc[mt][nt][0], acc[mt][nt][1]);
            float2 v1 = make_float2(acc[mt][nt][2], acc[mt][nt][3]);
            *reinterpret_cast<float2*>(C + (size_t)row * 4096 + col)       = v0;
            *reinterpret_cast<float2*>(C + (size_t)(row + 8) * 4096 + col) = v1;
        }
    }
}

// ------------------------- transform kernels --------------------------------
// Forward rDFT-4: X0=x0+x1+x2+x3, X2=x0-x1+x2-x3, Xr=x0-x2, Xi=x3-x1
__global__ void prep_x_kernel(const float* __restrict__ x) {
    int t = blockIdx.x * blockDim.x + threadIdx.x;
    if (t >= 4096 * 1024) return;
    int b = t >> 10, g = t & 1023;
    float4 v = *reinterpret_cast<const float4*>(x + ((size_t)b << 12) + (g << 2));
    float e = v.x + v.z, o = v.y + v.w;
    __half* r = g_Xt + ((size_t)b << 12);
    r[g]        = __float2half_rn(e + o);
    r[1024 + g] = __float2half_rn(e - o);
    r[2048 + g] = __float2half_rn(v.x - v.z);
    r[3072 + g] = __float2half_rn(v.w - v.y);
}

// Eigens -> W0, W2, W1 (complex bin packed as [[Er,-Ei],[Ei,Er]])
__global__ void prep_w_kernel(const float* __restrict__ eg) {
    int t = blockIdx.x * blockDim.x + threadIdx.x;
    if (t >= 1024 * 1024) return;
    int y = t >> 10, xg = t & 1023;
    float4 v = *reinterpret_cast<const float4*>(eg + ((size_t)t << 2));
    float e = v.x + v.z, o = v.y + v.w;
    __half Er  = __float2half_rn(v.x - v.z);
    __half Ei  = __float2half_rn(v.w - v.y);
    __half nEi = __float2half_rn(v.y - v.w);
    g_W0[t] = __float2half_rn(e + o);
    g_W2[t] = __float2half_rn(e - o);
    size_t r1 = (size_t)y * 2048;
    size_t r2 = (size_t)(1024 + y) * 2048;
    g_W1[r1 + xg]        = Er;
    g_W1[r1 + 1024 + xg] = nEi;
    g_W1[r2 + xg]        = Ei;
    g_W1[r2 + 1024 + xg] = Er;
}

// Inverse rDFT-4: out_j = (Y0 + (-1)^j Y2 + 2 Re(Y1 i^j)) / 4
__global__ void post_kernel(float* __restrict__ out) {
    int t = blockIdx.x * blockDim.x + threadIdx.x;
    if (t >= 4096 * 1024) return;
    int b = t >> 10, y = t & 1023;
    const float* r = g_Yt + ((size_t)b << 12);
    float Y0 = r[y], Y2 = r[1024 + y], Yr = r[2048 + y], Yi = r[3072 + y];
    float4 o;
    o.x = 0.25f * (Y0 + Y2 + 2.0f * Yr);
    o.y = 0.25f * (Y0 - Y2 - 2.0f * Yi);
    o.z = 0.25f * (Y0 + Y2 - 2.0f * Yr);
    o.w = 0.25f * (Y0 - Y2 + 2.0f * Yi);
    *reinterpret_cast<float4*>(out + ((size_t)b << 12) + (y << 2)) = o;
}

// ------------------------- host side ----------------------------------------
extern "C" void kernel_launch(void* const* d_in, const int* in_sizes, int n_in,
                              void* d_out, int out_size)
{
    const float* x  = (const float*)d_in[0];
    const float* eg = (const float*)d_in[1];
    if (n_in >= 2 && in_sizes[0] < in_sizes[1]) {   // x: 16.8M elems, eigens: 4.2M
        const float* t = x; x = eg; eg = t;
    }

    cudaFuncSetAttribute(gemm_f16_merged,
                         cudaFuncAttributeMaxDynamicSharedMemorySize, SMEM_GEMM);

    prep_x_kernel<<<(4096 * 1024) / 256, 256>>>(x);
    prep_w_kernel<<<(1024 * 1024) / 256, 256>>>(eg);
    gemm_f16_merged<<<1024, 256, SMEM_GEMM>>>();
    post_kernel<<<(4096 * 1024) / 256, 256>>>((float*)d_out);
}

// round 10
// speedup vs baseline: 1.8404x; 1.2049x over previous
#include <cuda_runtime.h>
#include <cuda_fp16.h>
#include <cstdint>

// ============================================================================
// CirculantLinear via length-4 real DFT diagonalization (sm_103-safe ISA:
// cp.async + ldmatrix + mma.sync.m16n8k16.f16; no tcgen05/TMA — harness
// compiles via compute_103 which rejects all "a"-suffix features).
//
//   x (4096x4096 f32), eigens (1024x1024x4 f32) -> out (4096x4096 f32)
//   prep_x : x -> Xt = [X0|X2|Xr|Xi]  (half)
//   prep_w : eigens -> W0, W2 (1024x1024), W1 (2048x2048 = [[Er,-Ei],[Ei,Er]])
//   ONE merged GEMM launch (1024 tiles, 3 logical GEMMs, f32 accum):
//       Yt[:,0:1024]   = X0 * W0^T
//       Yt[:,1024:2048]= X2 * W2^T
//       Yt[:,2048:4096]= [Xr|Xi] * W1^T
//   post   : inverse length-4 rDFT -> out
//
// R9: BK=64 per stage (4 k-subchunks/iter => half the barrier+wait events),
//     XOR bank swizzle (rows exactly 128B, conflict-free ldmatrix) keeps
//     3-stage smem at 96KB/CTA => 2 CTAs/SM retained.
// ============================================================================

// ------------------------- device scratch (static) --------------------------
__device__ __half g_Xt[(size_t)4096 * 4096];   // 32 MB
__device__ __half g_W0[1024 * 1024];           // 2 MB
__device__ __half g_W2[1024 * 1024];           // 2 MB
__device__ __half g_W1[(size_t)2048 * 2048];   // 8 MB
__device__ float  g_Yt[(size_t)4096 * 4096];   // 64 MB

// ------------------------- PTX helpers --------------------------------------
__device__ __forceinline__ uint32_t smem_u32(const void* p) {
    uint32_t a;
    asm("{ .reg .u64 t; cvta.to.shared.u64 t, %1; cvt.u32.u64 %0, t; }"
        : "=r"(a) : "l"(p));
    return a;
}

__device__ __forceinline__ void cp_async16(uint32_t dst, const void* src) {
    asm volatile("cp.async.cg.shared.global [%0], [%1], 16;"
                 :: "r"(dst), "l"(src) : "memory");
}
#define CP_COMMIT() asm volatile("cp.async.commit_group;" ::: "memory")
#define CP_WAIT(N)  asm volatile("cp.async.wait_group %0;" :: "n"(N) : "memory")

__device__ __forceinline__ void ldsm_x4(uint32_t r[4], uint32_t addr) {
    asm volatile("ldmatrix.sync.aligned.m8n8.x4.shared.b16 {%0,%1,%2,%3}, [%4];"
                 : "=r"(r[0]), "=r"(r[1]), "=r"(r[2]), "=r"(r[3]) : "r"(addr));
}

__device__ __forceinline__ void mma16816(float c[4], const uint32_t a[4],
                                         const uint32_t b[2]) {
    asm volatile(
        "mma.sync.aligned.m16n8k16.row.col.f32.f16.f16.f32 "
        "{%0,%1,%2,%3}, {%4,%5,%6,%7}, {%8,%9}, {%0,%1,%2,%3};"
        : "+f"(c[0]), "+f"(c[1]), "+f"(c[2]), "+f"(c[3])
        : "r"(a[0]), "r"(a[1]), "r"(a[2]), "r"(a[3]), "r"(b[0]), "r"(b[1]));
}

// ------------------------- merged GEMM kernel --------------------------------
// CTA tile 128x128, BK=64 halfs per stage, 3-stage cp.async pipeline,
// 2 CTAs/SM. 8 warps as 4(M) x 2(N): warp tile 32x64.
// smem rows are exactly 128 B (64 halfs = 8 chunks of 16 B); bank conflicts
// avoided with chunk' = chunk ^ (row & 7) XOR swizzle (each ldmatrix phase's
// 8 rows hit 8 distinct 16B chunk positions => disjoint bank quads).
static constexpr int BK = 64, STAGES = 3;
static constexpr int AB_BYTES  = 128 * 128;             // 16384 per operand
static constexpr int STG_BYTES = 2 * AB_BYTES;          // 32768 per stage
static constexpr int SMEM_GEMM = STAGES * STG_BYTES;    // 98304

// Tile table (1024 tiles):
//   t in [0,512):    W1 segment (nk2=32) — scheduled FIRST (long tiles)
//   t in [512,768):  W0 segment (nk2=16)
//   t in [768,1024): W2 segment (nk2=16)
__global__ void __launch_bounds__(256, 2) gemm_f16_merged()
{
    extern __shared__ __align__(128) char smem[];
    const uint32_t sb = smem_u32(smem);
    const int tid  = threadIdx.x;
    const int wid  = tid >> 5;
    const int lane = tid & 31;

    // ---- tile decode ----
    const __half* A;           // Xt column window, [4096 rows, lda=4096]
    const __half* B;           // [N, K] row-major (k contiguous)
    float*        C;           // Yt column window
    int ldb, nk2, m0, n0;
    {
        int t = blockIdx.x;
        if (t < 512) {                       // bin1: [Xr|Xi] * W1^T
            m0 = (t >> 4) * 128; n0 = (t & 15) * 128;
            A = g_Xt + 2048; B = g_W1; C = g_Yt + 2048; ldb = 2048; nk2 = 32;
        } else if (t < 768) {                // bin0: X0 * W0^T
            int u = t - 512;
            m0 = (u >> 3) * 128; n0 = (u & 7) * 128;
            A = g_Xt; B = g_W0; C = g_Yt; ldb = 1024; nk2 = 16;
        } else {                             // bin2: X2 * W2^T
            int u = t - 768;
            m0 = (u >> 3) * 128; n0 = (u & 7) * 128;
            A = g_Xt + 1024; B = g_W2; C = g_Yt + 1024; ldb = 1024; nk2 = 16;
        }
    }
    const int wm = wid & 3;          // M offset wm*32
    const int wn = wid >> 2;         // N offset wn*64

    const __half* Abase = A + (size_t)m0 * 4096;
    const __half* Bbase = B + (size_t)n0 * ldb;

    // --- stage loader: 1024 x 16B chunks each for A and B, 4 per thread ---
    auto load_stage = [&](int s, int kt2) {
        const uint32_t st = sb + s * STG_BYTES;
        const __half* Ag = Abase + kt2 * BK;
        const __half* Bg = Bbase + kt2 * BK;
        #pragma unroll
        for (int i = 0; i < 4; i++) {
            int seg = i * 256 + tid;          // 0..1023
            int row = seg >> 3, c = seg & 7;  // row 0..127, 16B chunk 0..7
            uint32_t so = row * 128 + ((c ^ (row & 7)) << 4);
            cp_async16(st + so,            Ag + (size_t)row * 4096 + c * 8);
            cp_async16(st + AB_BYTES + so, Bg + (size_t)row * ldb  + c * 8);
        }
    };

    float acc[2][8][4];
    #pragma unroll
    for (int mt = 0; mt < 2; mt++)
        #pragma unroll
        for (int nt = 0; nt < 8; nt++)
            #pragma unroll
            for (int i = 0; i < 4; i++) acc[mt][nt][i] = 0.0f;

    // ldmatrix lane addressing (rows + 16B-chunk index within 128B row)
    const int a_row = wm * 32 + (lane & 15);                      // + mt*16
    const int a_cb  = lane >> 4;                                  // chunk bit
    const int arx   = a_row & 7;                                  // swizzle key
    const int b_row = wn * 64 + (lane & 7) + ((lane >> 1) & 8);   // + np*16
    const int b_cb  = (lane >> 3) & 1;
    const int brx   = b_row & 7;

    // --- prologue: stages 0,1 ---
    load_stage(0, 0); CP_COMMIT();
    load_stage(1, 1); CP_COMMIT();

    // --- mainloop: ONE barrier per iteration (slot math as in R8) ---
    int slot = 0;
    for (int kt = 0; kt < nk2; kt++) {
        CP_WAIT(1);
        __syncthreads();

        int kn = kt + 2;
        if (kn < nk2) {
            int ls = slot + 2; if (ls >= 3) ls -= 3;
            load_stage(ls, kn);
        }
        CP_COMMIT();   // commit (possibly empty) keeps group accounting fixed

        const uint32_t As = sb + slot * STG_BYTES;
        const uint32_t Bs = As + AB_BYTES;

        #pragma unroll
        for (int ks = 0; ks < 4; ks++) {      // 4 x (K=16) subchunks
            uint32_t afr[2][4];
            #pragma unroll
            for (int mt = 0; mt < 2; mt++)
                ldsm_x4(afr[mt],
                        As + (a_row + mt * 16) * 128 +
                        (((2 * ks + a_cb) ^ arx) << 4));
            uint32_t bfr[8][2];
            #pragma unroll
            for (int np = 0; np < 4; np++) {
                uint32_t r[4];
                ldsm_x4(r, Bs + (b_row + np * 16) * 128 +
                           (((2 * ks + b_cb) ^ brx) << 4));
                bfr[np * 2 + 0][0] = r[0]; bfr[np * 2 + 0][1] = r[1];
                bfr[np * 2 + 1][0] = r[2]; bfr[np * 2 + 1][1] = r[3];
            }
            #pragma unroll
            for (int mt = 0; mt < 2; mt++)
                #pragma unroll
                for (int nt = 0; nt < 8; nt++)
                    mma16816(acc[mt][nt], afr[mt], bfr[nt]);
        }

        if (++slot == 3) slot = 0;
    }

    // --- epilogue: direct f32 stores to Yt ---
    const int g = lane >> 2, t4 = lane & 3;
    #pragma unroll
    for (int mt = 0; mt < 2; mt++) {
        int row = m0 + wm * 32 + mt * 16 + g;
        #pragma unroll
        for (int nt = 0; nt < 8; nt++) {
            int col = n0 + wn * 64 + nt * 8 + 2 * t4;
            float2 v0 = make_float2(acc[mt][nt][0], acc[mt][nt][1]);
            float2 v1 = make_float2(acc[mt][nt][2], acc[mt][nt][3]);
            *reinterpret_cast<float2*>(C + (size_t)row * 4096 + col)       = v0;
            *reinterpret_cast<float2*>(C + (size_t)(row + 8) * 4096 + col) = v1;
        }
    }
}

// ------------------------- transform kernels --------------------------------
// Forward rDFT-4: X0=x0+x1+x2+x3, X2=x0-x1+x2-x3, Xr=x0-x2, Xi=x3-x1
__global__ void prep_x_kernel(const float* __restrict__ x) {
    int t = blockIdx.x * blockDim.x + threadIdx.x;
    if (t >= 4096 * 1024) return;
    int b = t >> 10, g = t & 1023;
    float4 v = *reinterpret_cast<const float4*>(x + ((size_t)b << 12) + (g << 2));
    float e = v.x + v.z, o = v.y + v.w;
    __half* r = g_Xt + ((size_t)b << 12);
    r[g]        = __float2half_rn(e + o);
    r[1024 + g] = __float2half_rn(e - o);
    r[2048 + g] = __float2half_rn(v.x - v.z);
    r[3072 + g] = __float2half_rn(v.w - v.y);
}

// Eigens -> W0, W2, W1 (complex bin packed as [[Er,-Ei],[Ei,Er]])
__global__ void prep_w_kernel(const float* __restrict__ eg) {
    int t = blockIdx.x * blockDim.x + threadIdx.x;
    if (t >= 1024 * 1024) return;
    int y = t >> 10, xg = t & 1023;
    float4 v = *reinterpret_cast<const float4*>(eg + ((size_t)t << 2));
    float e = v.x + v.z, o = v.y + v.w;
    __half Er  = __float2half_rn(v.x - v.z);
    __half Ei  = __float2half_rn(v.w - v.y);
    __half nEi = __float2half_rn(v.y - v.w);
    g_W0[t] = __float2half_rn(e + o);
    g_W2[t] = __float2half_rn(e - o);
    size_t r1 = (size_t)y * 2048;
    size_t r2 = (size_t)(1024 + y) * 2048;
    g_W1[r1 + xg]        = Er;
    g_W1[r1 + 1024 + xg] = nEi;
    g_W1[r2 + xg]        = Ei;
    g_W1[r2 + 1024 + xg] = Er;
}

// Inverse rDFT-4: out_j = (Y0 + (-1)^j Y2 + 2 Re(Y1 i^j)) / 4
__global__ void post_kernel(float* __restrict__ out) {
    int t = blockIdx.x * blockDim.x + threadIdx.x;
    if (t >= 4096 * 1024) return;
    int b = t >> 10, y = t & 1023;
    const float* r = g_Yt + ((size_t)b << 12);
    float Y0 = r[y], Y2 = r[1024 + y], Yr = r[2048 + y], Yi = r[3072 + y];
    float4 o;
    o.x = 0.25f * (Y0 + Y2 + 2.0f * Yr);
    o.y = 0.25f * (Y0 - Y2 - 2.0f * Yi);
    o.z = 0.25f * (Y0 + Y2 - 2.0f * Yr);
    o.w = 0.25f * (Y0 - Y2 + 2.0f * Yi);
    *reinterpret_cast<float4*>(out + ((size_t)b << 12) + (y << 2)) = o;
}

// ------------------------- host side ----------------------------------------
extern "C" void kernel_launch(void* const* d_in, const int* in_sizes, int n_in,
                              void* d_out, int out_size)
{
    const float* x  = (const float*)d_in[0];
    const float* eg = (const float*)d_in[1];
    if (n_in >= 2 && in_sizes[0] < in_sizes[1]) {   // x: 16.8M elems, eigens: 4.2M
        const float* t = x; x = eg; eg = t;
    }

    cudaFuncSetAttribute(gemm_f16_merged,
                         cudaFuncAttributeMaxDynamicSharedMemorySize, SMEM_GEMM);

    prep_x_kernel<<<(4096 * 1024) / 256, 256>>>(x);
    prep_w_kernel<<<(1024 * 1024) / 256, 256>>>(eg);
    gemm_f16_merged<<<1024, 256, SMEM_GEMM>>>();
    post_kernel<<<(4096 * 1024) / 256, 256>>>((float*)d_out);
}